// round 5
// baseline (speedup 1.0000x reference)
#include <cuda_runtime.h>
#include <cuda_bf16.h>
#include <cstdint>
#include <math.h>

#define BB 4
#define SS 2048
#define DD 1024

// ---------------------------------------------------------------------------
// Scratch (device globals — allocation-free per harness rules)
// bf16 operand buffers use [hi | lo] layout: row length = 2*Kphys.
// ---------------------------------------------------------------------------
__device__ __nv_bfloat16 g_x3 [(size_t)BB * SS * 2 * DD];   // x split      [8192][2048]
__device__ __nv_bfloat16 g_wqt[(size_t)DD * 2 * DD];        // Wq^T split   [1024][2048]
__device__ __nv_bfloat16 g_wkt[(size_t)DD * 2 * DD];
__device__ __nv_bfloat16 g_wvt[(size_t)DD * 2 * DD];
__device__ __nv_bfloat16 g_q3 [(size_t)BB * SS * 2 * DD];   // q split
__device__ __nv_bfloat16 g_k3 [(size_t)BB * SS * 2 * DD];   // k split
__device__ float         g_vf [(size_t)BB * SS * DD];       // v fp32
__device__ __nv_bfloat16 g_vt3[(size_t)BB * DD * 2 * SS];   // v^T split  [b][1024][4096]
__device__ float         g_s  [(size_t)BB * SS * SS];       // raw scores fp32
__device__ __nv_bfloat16 g_a3 [(size_t)BB * SS * 2 * SS];   // attn split [b][2048][4096]

// ---------------------------------------------------------------------------
// PTX helpers (compute_103-safe: cp.async, ldmatrix, mma.sync only)
// ---------------------------------------------------------------------------
__device__ __forceinline__ void cp16(uint32_t dst, const void* src) {
    asm volatile("cp.async.cg.shared.global [%0], [%1], 16;\n" :: "r"(dst), "l"(src));
}
__device__ __forceinline__ uint32_t swz128(uint32_t off) { return off ^ ((off >> 3) & 0x70); }

__device__ __forceinline__ void ldsm4(uint32_t& r0, uint32_t& r1, uint32_t& r2, uint32_t& r3,
                                      uint32_t addr) {
    asm volatile("ldmatrix.sync.aligned.m8n8.x4.shared.b16 {%0,%1,%2,%3}, [%4];"
                 : "=r"(r0), "=r"(r1), "=r"(r2), "=r"(r3) : "r"(addr));
}

__device__ __forceinline__ void mma_bf16(float c[4], const uint32_t a[4], const uint32_t b0,
                                         const uint32_t b1) {
    asm volatile(
        "mma.sync.aligned.m16n8k16.row.col.f32.bf16.bf16.f32 "
        "{%0,%1,%2,%3}, {%4,%5,%6,%7}, {%8,%9}, {%0,%1,%2,%3};\n"
        : "+f"(c[0]), "+f"(c[1]), "+f"(c[2]), "+f"(c[3])
        : "r"(a[0]), "r"(a[1]), "r"(a[2]), "r"(a[3]), "r"(b0), "r"(b1));
}

// ---------------------------------------------------------------------------
// Persistent mma.sync GEMM. CTA tile 128x128, BK=64, 3-stage cp.async,
// 128 threads = 4 warps of 64x64 (ldmatrix.x4 fragments).
// 3 logical K-passes realize fp32 = hi+lo bf16 split:
//   A offsets {0,P,0}, B offsets {0,0,P}  (P = Kphys elements).
// sched 1: fused QKV   — A=x3; B0/1/2 = Wq^T/Wk^T/Wv^T; C0/1 split-bf16 q3/k3,
//                        C2 fp32 v.
// sched 2: scores QK^T — triangular causal tile list, C fp32.
// sched 3: attn @ V    — K clamped at diagonal block, longest tiles first.
// ---------------------------------------------------------------------------
#define NSTAGE 3
#define STAGE_BYTES 32768            // A 16KB + B 16KB
#define GEMM_SMEM (NSTAGE * STAGE_BYTES)
#define GRID_P 304                   // 2 CTAs/SM * 152 SMs (GB300)

__global__ __launch_bounds__(128, 2)
void gemm_persist(int sched, int ntiles,
                  const __nv_bfloat16* __restrict__ A,
                  const __nv_bfloat16* __restrict__ B0,
                  const __nv_bfloat16* __restrict__ B1,
                  const __nv_bfloat16* __restrict__ B2,
                  void* __restrict__ C0, void* __restrict__ C1, void* __restrict__ C2)
{
    extern __shared__ __align__(1024) char smem[];
    const uint32_t base0 = (uint32_t)__cvta_generic_to_shared(smem);

    const int tid  = threadIdx.x;
    const int wid  = tid >> 5;
    const int lane = tid & 31;
    const int wm   = wid >> 1;      // 0..1
    const int wn   = wid & 1;       // 0..1

    // ldmatrix fragment offsets within a stage (rows of 128B, SW128 swizzle)
    const int mo  = ((lane >> 3) & 1) * 8 + (lane & 7);
    const int akb = ((lane >> 4) & 1) * 16;
    const int no  = ((lane >> 4) & 1) * 8 + (lane & 7);
    const int bkb = ((lane >> 3) & 1) * 16;
    uint32_t aoff[4][4], boff[4][4];
    #pragma unroll
    for (int ks = 0; ks < 4; ks++)
        #pragma unroll
        for (int f = 0; f < 4; f++) {
            aoff[ks][f] = swz128((uint32_t)((wm * 64 + f * 16 + mo) * 128 + ks * 32 + akb));
            boff[ks][f] = swz128((uint32_t)((wn * 64 + f * 16 + no) * 128 + ks * 32 + bkb));
        }

    for (int t = blockIdx.x; t < ntiles; t += gridDim.x) {
        // ---- decode tile ----
        const __nv_bfloat16 *Ag, *Bg;
        void* Cv;
        int m0, n0, N_C, rowL, nCk, mode, P;
        if (sched == 1) {                       // fused QKV
            const int m  = t / 24;
            const int nn = t - m * 24;
            const int w  = nn >> 3;
            m0 = m * 128; n0 = (nn & 7) * 128;
            Ag = A;
            Bg = (w == 0) ? B0 : ((w == 1) ? B1 : B2);
            Cv = (w == 0) ? C0 : ((w == 1) ? C1 : C2);
            mode = (w == 2) ? 0 : 1;
            N_C = DD; rowL = 2 * DD; nCk = DD / 64; P = DD;
        } else if (sched == 2) {                // scores, triangular decode
            const int z  = t / 136;
            const int tt = t - z * 136;
            int r = (int)floorf((sqrtf(8.0f * tt + 1.0f) - 1.0f) * 0.5f);
            while ((r + 1) * (r + 2) / 2 <= tt) r++;
            while (r * (r + 1) / 2 > tt) r--;
            const int c = tt - r * (r + 1) / 2;
            m0 = r * 128; n0 = c * 128;
            Ag = A  + (size_t)z * SS * 2 * DD;
            Bg = B0 + (size_t)z * SS * 2 * DD;
            Cv = (float*)C0 + (size_t)z * SS * SS;
            mode = 0; N_C = SS; rowL = 2 * DD; nCk = DD / 64; P = DD;
        } else {                                // attn @ V, longest-first
            const int m    = 15 - (t >> 5);
            const int rest = t & 31;
            m0 = m * 128; n0 = (rest & 7) * 128;
            const int z = rest >> 3;
            Ag = A  + (size_t)z * SS * 2 * SS;
            Bg = B0 + (size_t)z * DD * 2 * SS;
            Cv = (float*)C0 + (size_t)z * SS * DD;
            mode = 0; N_C = DD; rowL = 2 * SS;
            nCk = min(SS / 64, 2 * m + 2); P = SS;
        }
        const int nC = 3 * nCk;

        float acc[4][8][4];
        #pragma unroll
        for (int i = 0; i < 4; i++)
            #pragma unroll
            for (int j = 0; j < 8; j++)
                #pragma unroll
                for (int q = 0; q < 4; q++) acc[i][j][q] = 0.0f;

        // chunk loader: thread t loads A row m0+tid and B row n0+tid (128B each)
        auto load_chunk = [&](int c) {
            const int st = c % NSTAGE;
            const int p  = c / nCk;
            const int ip = c - p * nCk;
            const int pA = (p == 1) ? P : 0;
            const int pB = (p == 2) ? P : 0;
            const uint32_t aBase = base0 + st * STAGE_BYTES;
            const uint32_t bBase = aBase + 16384;
            const __nv_bfloat16* as = Ag + (size_t)(m0 + tid) * rowL + pA + ip * 64;
            const __nv_bfloat16* bs = Bg + (size_t)(n0 + tid) * rowL + pB + ip * 64;
            const uint32_t ro = (uint32_t)tid * 128;
            #pragma unroll
            for (int s8 = 0; s8 < 8; s8++) {
                cp16(aBase + swz128(ro + s8 * 16), as + s8 * 8);
                cp16(bBase + swz128(ro + s8 * 16), bs + s8 * 8);
            }
            asm volatile("cp.async.commit_group;\n");
        };

        load_chunk(0);
        if (nC > 1) load_chunk(1);

        for (int c = 0; c < nC; ++c) {
            if (c + 1 < nC) asm volatile("cp.async.wait_group 1;\n" ::: "memory");
            else            asm volatile("cp.async.wait_group 0;\n" ::: "memory");
            __syncthreads();

            if (c + 2 < nC) load_chunk(c + 2);

            const uint32_t aB = base0 + (c % NSTAGE) * STAGE_BYTES;
            const uint32_t bB = aB + 16384;

            #pragma unroll
            for (int ks = 0; ks < 4; ks++) {
                uint32_t af[4][4], bf[4][4];
                #pragma unroll
                for (int f = 0; f < 4; f++)
                    ldsm4(af[f][0], af[f][1], af[f][2], af[f][3], aB + aoff[ks][f]);
                #pragma unroll
                for (int f = 0; f < 4; f++)
                    ldsm4(bf[f][0], bf[f][1], bf[f][2], bf[f][3], bB + boff[ks][f]);
                #pragma unroll
                for (int im = 0; im < 4; im++)
                    #pragma unroll
                    for (int jn = 0; jn < 8; jn++)
                        mma_bf16(acc[im][jn], af[im],
                                 bf[jn >> 1][(jn & 1) * 2], bf[jn >> 1][(jn & 1) * 2 + 1]);
            }
        }

        // ---- epilogue ----
        #pragma unroll
        for (int im = 0; im < 4; im++) {
            const int r = m0 + wm * 64 + im * 16 + (lane >> 2);
            #pragma unroll
            for (int jn = 0; jn < 8; jn++) {
                const int cc = n0 + wn * 64 + jn * 8 + (lane & 3) * 2;
                if (mode == 0) {
                    float* Cg = (float*)Cv;
                    *(float2*)(Cg + (size_t)r * N_C + cc)       = make_float2(acc[im][jn][0], acc[im][jn][1]);
                    *(float2*)(Cg + (size_t)(r + 8) * N_C + cc) = make_float2(acc[im][jn][2], acc[im][jn][3]);
                } else {
                    __nv_bfloat16* Cg = (__nv_bfloat16*)Cv;
                    #pragma unroll
                    for (int hr = 0; hr < 2; hr++) {
                        const float v0 = acc[im][jn][hr * 2];
                        const float v1 = acc[im][jn][hr * 2 + 1];
                        const __nv_bfloat16 h0 = __float2bfloat16(v0);
                        const __nv_bfloat16 l0 = __float2bfloat16(v0 - __bfloat162float(h0));
                        const __nv_bfloat16 h1 = __float2bfloat16(v1);
                        const __nv_bfloat16 l1 = __float2bfloat16(v1 - __bfloat162float(h1));
                        __nv_bfloat16* row = Cg + (size_t)(r + hr * 8) * (2 * N_C);
                        *(__nv_bfloat162*)(row + cc)       = __halves2bfloat162(h0, h1);
                        *(__nv_bfloat162*)(row + N_C + cc) = __halves2bfloat162(l0, l1);
                    }
                }
            }
        }
        __syncthreads();   // protect SMEM stages before next tile's prefetch
    }
}

// ---------------------------------------------------------------------------
// fp32 -> [hi | lo] bf16 split, same row layout (row len 2K).
// ---------------------------------------------------------------------------
__global__ __launch_bounds__(256)
void conv_split2(const float* __restrict__ src, __nv_bfloat16* __restrict__ dst, int K)
{
    const long long idx = (long long)blockIdx.x * 256 + threadIdx.x;
    const long long m = idx / K;
    const int j = (int)(idx % K);
    const float v = src[idx];
    const __nv_bfloat16 h = __float2bfloat16(v);
    const __nv_bfloat16 l = __float2bfloat16(v - __bfloat162float(h));
    __nv_bfloat16* o = dst + m * 2LL * K;
    o[j] = h; o[K + j] = l;
}

// ---------------------------------------------------------------------------
// fp32 [R][C] -> transposed split bf16 [C][2R] (hi | lo)
// ---------------------------------------------------------------------------
__global__ __launch_bounds__(256)
void transposeY2(const float* __restrict__ src, __nv_bfloat16* __restrict__ dst,
                 int R, int C, long long sSrc, long long sDst)
{
    __shared__ float tile[32][33];
    src += (long long)blockIdx.z * sSrc;
    dst += (long long)blockIdx.z * sDst;
    const int r0 = blockIdx.y * 32, c0 = blockIdx.x * 32;
    const int tx = threadIdx.x & 31;
    const int ty = threadIdx.x >> 5;

    #pragma unroll
    for (int dy = 0; dy < 32; dy += 8)
        tile[ty + dy][tx] = src[(size_t)(r0 + ty + dy) * C + c0 + tx];
    __syncthreads();

    #pragma unroll
    for (int dy = 0; dy < 32; dy += 8) {
        const int c = c0 + ty + dy;
        const int r = r0 + tx;
        const float v = tile[tx][ty + dy];
        const __nv_bfloat16 h = __float2bfloat16(v);
        const __nv_bfloat16 l = __float2bfloat16(v - __bfloat162float(h));
        __nv_bfloat16* o = dst + (size_t)c * 2 * R;
        o[r] = h; o[R + r] = l;
    }
}

// ---------------------------------------------------------------------------
// Causal softmax emitting split bf16 attn [hi | lo]. Zero-fills only up to the
// 128-row diagonal-block boundary (the AV GEMM K-clamp never reads past it).
// ---------------------------------------------------------------------------
__global__ __launch_bounds__(256)
void softmax2(const float* __restrict__ Sc, __nv_bfloat16* __restrict__ A3,
              int S, float scale)
{
    const long long row = blockIdx.x;            // b*S + i
    const int i = (int)(row % S);
    const float* p = Sc + row * (long long)S;
    __nv_bfloat16* out = A3 + row * (long long)(2 * S);
    const int L = i + 1;
    const int Lz = ((i >> 7) + 1) << 7;          // diagonal-block end

    const int tid  = threadIdx.x;
    const int lane = tid & 31;
    const int wid  = tid >> 5;
    __shared__ float red[32];

    float mx = -INFINITY;
    for (int j = tid; j < L; j += 256) mx = fmaxf(mx, p[j]);
    #pragma unroll
    for (int o = 16; o; o >>= 1) mx = fmaxf(mx, __shfl_xor_sync(0xffffffffu, mx, o));
    if (lane == 0) red[wid] = mx;
    __syncthreads();
    if (tid == 0) {
        float m = red[0];
        #pragma unroll
        for (int w = 1; w < 8; w++) m = fmaxf(m, red[w]);
        red[0] = m;
    }
    __syncthreads();
    mx = red[0];
    __syncthreads();

    float e[8];
    float sum = 0.0f;
    int cnt = 0;
    for (int j = tid; j < L; j += 256) {
        const float ev = __expf((p[j] - mx) * scale);
        e[cnt++] = ev;
        sum += ev;
    }
    #pragma unroll
    for (int o = 16; o; o >>= 1) sum += __shfl_xor_sync(0xffffffffu, sum, o);
    if (lane == 0) red[wid] = sum;
    __syncthreads();
    if (tid == 0) {
        float s = red[0];
        #pragma unroll
        for (int w = 1; w < 8; w++) s += red[w];
        red[0] = s;
    }
    __syncthreads();
    const float inv = 1.0f / red[0];

    cnt = 0;
    for (int j = tid; j < L; j += 256) {
        const float v = e[cnt++] * inv;
        const __nv_bfloat16 h = __float2bfloat16(v);
        const __nv_bfloat16 l = __float2bfloat16(v - __bfloat162float(h));
        out[j] = h; out[S + j] = l;
    }
    const __nv_bfloat16 zero = __float2bfloat16(0.0f);
    for (int j = L + tid; j < Lz; j += 256) {
        out[j] = zero; out[S + j] = zero;
    }
}

// ---------------------------------------------------------------------------
extern "C" void kernel_launch(void* const* d_in, const int* in_sizes, int n_in,
                              void* d_out, int out_size)
{
    (void)in_sizes; (void)n_in; (void)out_size;
    const float* x  = (const float*)d_in[0];
    const float* Wq = (const float*)d_in[1];
    const float* Wk = (const float*)d_in[2];
    const float* Wv = (const float*)d_in[3];
    float* out = (float*)d_out;

    __nv_bfloat16 *x3, *wqt, *wkt, *wvt, *q3, *k3, *vt3, *a3;
    float *vf, *s;
    cudaGetSymbolAddress((void**)&x3,  g_x3);
    cudaGetSymbolAddress((void**)&wqt, g_wqt);
    cudaGetSymbolAddress((void**)&wkt, g_wkt);
    cudaGetSymbolAddress((void**)&wvt, g_wvt);
    cudaGetSymbolAddress((void**)&q3,  g_q3);
    cudaGetSymbolAddress((void**)&k3,  g_k3);
    cudaGetSymbolAddress((void**)&vf,  g_vf);
    cudaGetSymbolAddress((void**)&vt3, g_vt3);
    cudaGetSymbolAddress((void**)&s,   g_s);
    cudaGetSymbolAddress((void**)&a3,  g_a3);

    cudaFuncSetAttribute(gemm_persist, cudaFuncAttributeMaxDynamicSharedMemorySize, GEMM_SMEM);

    const int B = BB, S = SS, D = DD;
    const long long MS = (long long)B * S;   // 8192

    // 1) operand conversion
    conv_split2<<<(int)(MS * D / 256), 256>>>(x, x3, D);
    {
        dim3 tg(D / 32, D / 32, 1);
        transposeY2<<<tg, 256>>>(Wq, wqt, D, D, 0, 0);
        transposeY2<<<tg, 256>>>(Wk, wkt, D, D, 0, 0);
        transposeY2<<<tg, 256>>>(Wv, wvt, D, D, 0, 0);
    }

    // 2) fused QKV projections (persistent): 64 m-tiles x 24 n-tiles
    gemm_persist<<<GRID_P, 128, GEMM_SMEM>>>(1, 64 * 24, x3, wqt, wkt, wvt,
                                             q3, k3, vf);

    // 3) transpose-split v
    {
        dim3 tg(D / 32, S / 32, B);
        transposeY2<<<tg, 256>>>(vf, vt3, S, D,
                                 (long long)S * D, (long long)D * 2 * S);
    }

    // 4) scores = Q K^T (persistent, triangular tile list: 136 per batch)
    gemm_persist<<<GRID_P, 128, GEMM_SMEM>>>(2, 136 * B, q3, k3, nullptr, nullptr,
                                             s, nullptr, nullptr);

    // 5) softmax -> split bf16 attn
    softmax2<<<B * S, 256>>>(s, a3, S, 0.03125f);

    // 6) out = attn @ V (persistent, K-clamped, longest tiles first)
    gemm_persist<<<GRID_P, 128, GEMM_SMEM>>>(3, 16 * 8 * B, a3, vt3, nullptr, nullptr,
                                             out, nullptr, nullptr);
}

// round 6
// speedup vs baseline: 1.1524x; 1.1524x over previous
#include <cuda_runtime.h>
#include <cuda_bf16.h>
#include <cstdint>
#include <math.h>

#define BB 4
#define SS 2048
#define DD 1024

// ---------------------------------------------------------------------------
// Scratch (device globals — allocation-free per harness rules)
// bf16 operand buffers use [hi | lo] layout: row length = 2*Kphys.
// ---------------------------------------------------------------------------
__device__ __nv_bfloat16 g_x3 [(size_t)BB * SS * 2 * DD];   // x split      [8192][2048]
__device__ __nv_bfloat16 g_wqt[(size_t)DD * 2 * DD];        // Wq^T split   [1024][2048]
__device__ __nv_bfloat16 g_wkt[(size_t)DD * 2 * DD];
__device__ __nv_bfloat16 g_wvt[(size_t)DD * 2 * DD];
__device__ __nv_bfloat16 g_q3 [(size_t)BB * SS * 2 * DD];   // q split
__device__ __nv_bfloat16 g_k3 [(size_t)BB * SS * 2 * DD];   // k split
__device__ float         g_vf [(size_t)BB * SS * DD];       // v fp32
__device__ __nv_bfloat16 g_vt3[(size_t)BB * DD * 2 * SS];   // v^T split  [b][1024][4096]
__device__ float         g_s  [(size_t)BB * SS * SS];       // raw scores fp32
__device__ __nv_bfloat16 g_a3 [(size_t)BB * SS * 2 * SS];   // attn split [b][2048][4096]

// ---------------------------------------------------------------------------
// PTX helpers (compute_103-safe: cp.async, ldmatrix, mma.sync only)
// ---------------------------------------------------------------------------
__device__ __forceinline__ void cp16(uint32_t dst, const void* src) {
    asm volatile("cp.async.cg.shared.global [%0], [%1], 16;\n" :: "r"(dst), "l"(src));
}
__device__ __forceinline__ uint32_t swz128(uint32_t off) { return off ^ ((off >> 3) & 0x70); }

__device__ __forceinline__ void ldsm4(uint32_t& r0, uint32_t& r1, uint32_t& r2, uint32_t& r3,
                                      uint32_t addr) {
    asm volatile("ldmatrix.sync.aligned.m8n8.x4.shared.b16 {%0,%1,%2,%3}, [%4];"
                 : "=r"(r0), "=r"(r1), "=r"(r2), "=r"(r3) : "r"(addr));
}

__device__ __forceinline__ void mma_bf16(float c[4], const uint32_t a[4], const uint32_t b0,
                                         const uint32_t b1) {
    asm volatile(
        "mma.sync.aligned.m16n8k16.row.col.f32.bf16.bf16.f32 "
        "{%0,%1,%2,%3}, {%4,%5,%6,%7}, {%8,%9}, {%0,%1,%2,%3};\n"
        : "+f"(c[0]), "+f"(c[1]), "+f"(c[2]), "+f"(c[3])
        : "r"(a[0]), "r"(a[1]), "r"(a[2]), "r"(a[3]), "r"(b0), "r"(b1));
}

// ---------------------------------------------------------------------------
// mma.sync GEMM, flat 1-D grid, tile decode by sched. CTA tile 128x128, BK=64,
// 3-stage cp.async, 128 threads = 4 warps of 64x64, ldmatrix.x4 fragments with
// register double-buffering (prefetch ks+1 while issuing ks MMAs).
// 3 logical K-passes realize fp32 = hi+lo bf16 split:
//   A offsets {0,P,0}, B offsets {0,0,P}  (P = Kphys elements).
// sched 1: fused QKV (w = t>>9 selects Wq/Wk/Wv; q/k epilogue emits split bf16)
// sched 2: scores QK^T, triangular causal tile list (136 tiles per batch)
// sched 3: attn @ V, K clamped at diagonal block, longest tiles first
// ---------------------------------------------------------------------------
#define NSTAGE 3
#define STAGE_BYTES 32768            // A 16KB + B 16KB
#define GEMM_SMEM (NSTAGE * STAGE_BYTES)

__global__ __launch_bounds__(128, 2)
void gemm_mma(int sched,
              const __nv_bfloat16* __restrict__ A,
              const __nv_bfloat16* __restrict__ B0,
              const __nv_bfloat16* __restrict__ B1,
              const __nv_bfloat16* __restrict__ B2,
              void* __restrict__ C0, void* __restrict__ C1, void* __restrict__ C2)
{
    extern __shared__ __align__(1024) char smem[];
    const uint32_t base0 = (uint32_t)__cvta_generic_to_shared(smem);

    const int tid  = threadIdx.x;
    const int wid  = tid >> 5;
    const int lane = tid & 31;
    const int wm   = wid >> 1;      // 0..1
    const int wn   = wid & 1;       // 0..1

    // ---- decode tile ----
    const int t = blockIdx.x;
    const __nv_bfloat16 *Ag, *Bg;
    void* Cv;
    int m0, n0, N_C, rowL, nCk, mode, P;
    if (sched == 1) {                       // fused QKV
        const int w = t >> 9;
        const int r = t & 511;
        m0 = (r >> 3) * 128; n0 = (r & 7) * 128;
        Ag = A;
        Bg = (w == 0) ? B0 : ((w == 1) ? B1 : B2);
        Cv = (w == 0) ? C0 : ((w == 1) ? C1 : C2);
        mode = (w == 2) ? 0 : 1;
        N_C = DD; rowL = 2 * DD; nCk = DD / 64; P = DD;
    } else if (sched == 2) {                // scores, triangular decode
        const int z  = t / 136;
        const int tt = t - z * 136;
        int r = (int)floorf((sqrtf(8.0f * tt + 1.0f) - 1.0f) * 0.5f);
        while ((r + 1) * (r + 2) / 2 <= tt) r++;
        while (r * (r + 1) / 2 > tt) r--;
        const int c = tt - r * (r + 1) / 2;
        m0 = r * 128; n0 = c * 128;
        Ag = A  + (size_t)z * SS * 2 * DD;
        Bg = B0 + (size_t)z * SS * 2 * DD;
        Cv = (float*)C0 + (size_t)z * SS * SS;
        mode = 0; N_C = SS; rowL = 2 * DD; nCk = DD / 64; P = DD;
    } else {                                // attn @ V, longest-first
        const int m    = 15 - (t >> 5);
        const int rest = t & 31;
        m0 = m * 128; n0 = (rest & 7) * 128;
        const int z = rest >> 3;
        Ag = A  + (size_t)z * SS * 2 * SS;
        Bg = B0 + (size_t)z * DD * 2 * SS;
        Cv = (float*)C0 + (size_t)z * SS * DD;
        mode = 0; N_C = DD; rowL = 2 * SS;
        nCk = min(SS / 64, 2 * m + 2); P = SS;
    }
    const int nC = 3 * nCk;

    // ldmatrix fragment offsets within a stage (rows of 128B, SW128 swizzle)
    const int mo  = ((lane >> 3) & 1) * 8 + (lane & 7);
    const int akb = ((lane >> 4) & 1) * 16;
    const int no  = ((lane >> 4) & 1) * 8 + (lane & 7);
    const int bkb = ((lane >> 3) & 1) * 16;
    uint32_t aoff[4][4], boff[4][4];
    #pragma unroll
    for (int ks = 0; ks < 4; ks++)
        #pragma unroll
        for (int f = 0; f < 4; f++) {
            aoff[ks][f] = swz128((uint32_t)((wm * 64 + f * 16 + mo) * 128 + ks * 32 + akb));
            boff[ks][f] = swz128((uint32_t)((wn * 64 + f * 16 + no) * 128 + ks * 32 + bkb));
        }

    float acc[4][8][4];
    #pragma unroll
    for (int i = 0; i < 4; i++)
        #pragma unroll
        for (int j = 0; j < 8; j++)
            #pragma unroll
            for (int q = 0; q < 4; q++) acc[i][j][q] = 0.0f;

    // chunk loader: thread loads A row m0+tid and B row n0+tid (128B each)
    auto load_chunk = [&](int c) {
        const int st = c % NSTAGE;
        const int p  = c / nCk;
        const int ip = c - p * nCk;
        const int pA = (p == 1) ? P : 0;
        const int pB = (p == 2) ? P : 0;
        const uint32_t aBase = base0 + st * STAGE_BYTES;
        const uint32_t bBase = aBase + 16384;
        const __nv_bfloat16* as = Ag + (size_t)(m0 + tid) * rowL + pA + ip * 64;
        const __nv_bfloat16* bs = Bg + (size_t)(n0 + tid) * rowL + pB + ip * 64;
        const uint32_t ro = (uint32_t)tid * 128;
        #pragma unroll
        for (int s8 = 0; s8 < 8; s8++) {
            cp16(aBase + swz128(ro + s8 * 16), as + s8 * 8);
            cp16(bBase + swz128(ro + s8 * 16), bs + s8 * 8);
        }
        asm volatile("cp.async.commit_group;\n");
    };

    load_chunk(0);
    if (nC > 1) load_chunk(1);

    uint32_t af[2][4][4], bf[2][4][4];

    for (int c = 0; c < nC; ++c) {
        if (c + 1 < nC) asm volatile("cp.async.wait_group 1;\n" ::: "memory");
        else            asm volatile("cp.async.wait_group 0;\n" ::: "memory");
        __syncthreads();

        if (c + 2 < nC) load_chunk(c + 2);

        const uint32_t aB = base0 + (c % NSTAGE) * STAGE_BYTES;
        const uint32_t bB = aB + 16384;

        // prime ks=0 fragments
        #pragma unroll
        for (int f = 0; f < 4; f++)
            ldsm4(af[0][f][0], af[0][f][1], af[0][f][2], af[0][f][3], aB + aoff[0][f]);
        #pragma unroll
        for (int f = 0; f < 4; f++)
            ldsm4(bf[0][f][0], bf[0][f][1], bf[0][f][2], bf[0][f][3], bB + boff[0][f]);

        #pragma unroll
        for (int ks = 0; ks < 4; ks++) {
            const int p = ks & 1;
            if (ks < 3) {               // prefetch next ks while issuing MMAs
                const int q = 1 - p;
                #pragma unroll
                for (int f = 0; f < 4; f++)
                    ldsm4(af[q][f][0], af[q][f][1], af[q][f][2], af[q][f][3],
                          aB + aoff[ks + 1][f]);
                #pragma unroll
                for (int f = 0; f < 4; f++)
                    ldsm4(bf[q][f][0], bf[q][f][1], bf[q][f][2], bf[q][f][3],
                          bB + boff[ks + 1][f]);
            }
            #pragma unroll
            for (int im = 0; im < 4; im++)
                #pragma unroll
                for (int jn = 0; jn < 8; jn++)
                    mma_bf16(acc[im][jn], af[p][im],
                             bf[p][jn >> 1][(jn & 1) * 2], bf[p][jn >> 1][(jn & 1) * 2 + 1]);
        }
    }

    // ---- epilogue ----
    #pragma unroll
    for (int im = 0; im < 4; im++) {
        const int r = m0 + wm * 64 + im * 16 + (lane >> 2);
        #pragma unroll
        for (int jn = 0; jn < 8; jn++) {
            const int cc = n0 + wn * 64 + jn * 8 + (lane & 3) * 2;
            if (mode == 0) {
                float* Cg = (float*)Cv;
                *(float2*)(Cg + (size_t)r * N_C + cc)       = make_float2(acc[im][jn][0], acc[im][jn][1]);
                *(float2*)(Cg + (size_t)(r + 8) * N_C + cc) = make_float2(acc[im][jn][2], acc[im][jn][3]);
            } else {
                __nv_bfloat16* Cg = (__nv_bfloat16*)Cv;
                #pragma unroll
                for (int hr = 0; hr < 2; hr++) {
                    const float v0 = acc[im][jn][hr * 2];
                    const float v1 = acc[im][jn][hr * 2 + 1];
                    const __nv_bfloat16 h0 = __float2bfloat16(v0);
                    const __nv_bfloat16 l0 = __float2bfloat16(v0 - __bfloat162float(h0));
                    const __nv_bfloat16 h1 = __float2bfloat16(v1);
                    const __nv_bfloat16 l1 = __float2bfloat16(v1 - __bfloat162float(h1));
                    __nv_bfloat16* row = Cg + (size_t)(r + hr * 8) * (2 * N_C);
                    *(__nv_bfloat162*)(row + cc)       = __halves2bfloat162(h0, h1);
                    *(__nv_bfloat162*)(row + N_C + cc) = __halves2bfloat162(l0, l1);
                }
            }
        }
    }
}

// ---------------------------------------------------------------------------
// fp32 -> [hi | lo] bf16 split, same row layout (row len 2K).
// ---------------------------------------------------------------------------
__global__ __launch_bounds__(256)
void conv_split2(const float* __restrict__ src, __nv_bfloat16* __restrict__ dst, int K)
{
    const long long idx = (long long)blockIdx.x * 256 + threadIdx.x;
    const long long m = idx / K;
    const int j = (int)(idx % K);
    const float v = src[idx];
    const __nv_bfloat16 h = __float2bfloat16(v);
    const __nv_bfloat16 l = __float2bfloat16(v - __bfloat162float(h));
    __nv_bfloat16* o = dst + m * 2LL * K;
    o[j] = h; o[K + j] = l;
}

// ---------------------------------------------------------------------------
// fp32 [R][C] -> transposed split bf16 [C][2R] (hi | lo)
// ---------------------------------------------------------------------------
__global__ __launch_bounds__(256)
void transposeY2(const float* __restrict__ src, __nv_bfloat16* __restrict__ dst,
                 int R, int C, long long sSrc, long long sDst)
{
    __shared__ float tile[32][33];
    src += (long long)blockIdx.z * sSrc;
    dst += (long long)blockIdx.z * sDst;
    const int r0 = blockIdx.y * 32, c0 = blockIdx.x * 32;
    const int tx = threadIdx.x & 31;
    const int ty = threadIdx.x >> 5;

    #pragma unroll
    for (int dy = 0; dy < 32; dy += 8)
        tile[ty + dy][tx] = src[(size_t)(r0 + ty + dy) * C + c0 + tx];
    __syncthreads();

    #pragma unroll
    for (int dy = 0; dy < 32; dy += 8) {
        const int c = c0 + ty + dy;
        const int r = r0 + tx;
        const float v = tile[tx][ty + dy];
        const __nv_bfloat16 h = __float2bfloat16(v);
        const __nv_bfloat16 l = __float2bfloat16(v - __bfloat162float(h));
        __nv_bfloat16* o = dst + (size_t)c * 2 * R;
        o[r] = h; o[R + r] = l;
    }
}

// ---------------------------------------------------------------------------
// Causal softmax emitting split bf16 attn [hi | lo]. Zero-fills only up to the
// 128-row diagonal-block boundary (the AV GEMM K-clamp never reads past it).
// ---------------------------------------------------------------------------
__global__ __launch_bounds__(256)
void softmax2(const float* __restrict__ Sc, __nv_bfloat16* __restrict__ A3,
              int S, float scale)
{
    const long long row = blockIdx.x;            // b*S + i
    const int i = (int)(row % S);
    const float* p = Sc + row * (long long)S;
    __nv_bfloat16* out = A3 + row * (long long)(2 * S);
    const int L = i + 1;
    const int Lz = ((i >> 7) + 1) << 7;          // diagonal-block end

    const int tid  = threadIdx.x;
    const int lane = tid & 31;
    const int wid  = tid >> 5;
    __shared__ float red[32];

    float mx = -INFINITY;
    for (int j = tid; j < L; j += 256) mx = fmaxf(mx, p[j]);
    #pragma unroll
    for (int o = 16; o; o >>= 1) mx = fmaxf(mx, __shfl_xor_sync(0xffffffffu, mx, o));
    if (lane == 0) red[wid] = mx;
    __syncthreads();
    if (tid == 0) {
        float m = red[0];
        #pragma unroll
        for (int w = 1; w < 8; w++) m = fmaxf(m, red[w]);
        red[0] = m;
    }
    __syncthreads();
    mx = red[0];
    __syncthreads();

    float e[8];
    float sum = 0.0f;
    int cnt = 0;
    for (int j = tid; j < L; j += 256) {
        const float ev = __expf((p[j] - mx) * scale);
        e[cnt++] = ev;
        sum += ev;
    }
    #pragma unroll
    for (int o = 16; o; o >>= 1) sum += __shfl_xor_sync(0xffffffffu, sum, o);
    if (lane == 0) red[wid] = sum;
    __syncthreads();
    if (tid == 0) {
        float s = red[0];
        #pragma unroll
        for (int w = 1; w < 8; w++) s += red[w];
        red[0] = s;
    }
    __syncthreads();
    const float inv = 1.0f / red[0];

    cnt = 0;
    for (int j = tid; j < L; j += 256) {
        const float v = e[cnt++] * inv;
        const __nv_bfloat16 h = __float2bfloat16(v);
        const __nv_bfloat16 l = __float2bfloat16(v - __bfloat162float(h));
        out[j] = h; out[S + j] = l;
    }
    const __nv_bfloat16 zero = __float2bfloat16(0.0f);
    for (int j = L + tid; j < Lz; j += 256) {
        out[j] = zero; out[S + j] = zero;
    }
}

// ---------------------------------------------------------------------------
extern "C" void kernel_launch(void* const* d_in, const int* in_sizes, int n_in,
                              void* d_out, int out_size)
{
    (void)in_sizes; (void)n_in; (void)out_size;
    const float* x  = (const float*)d_in[0];
    const float* Wq = (const float*)d_in[1];
    const float* Wk = (const float*)d_in[2];
    const float* Wv = (const float*)d_in[3];
    float* out = (float*)d_out;

    __nv_bfloat16 *x3, *wqt, *wkt, *wvt, *q3, *k3, *vt3, *a3;
    float *vf, *s;
    cudaGetSymbolAddress((void**)&x3,  g_x3);
    cudaGetSymbolAddress((void**)&wqt, g_wqt);
    cudaGetSymbolAddress((void**)&wkt, g_wkt);
    cudaGetSymbolAddress((void**)&wvt, g_wvt);
    cudaGetSymbolAddress((void**)&q3,  g_q3);
    cudaGetSymbolAddress((void**)&k3,  g_k3);
    cudaGetSymbolAddress((void**)&vf,  g_vf);
    cudaGetSymbolAddress((void**)&vt3, g_vt3);
    cudaGetSymbolAddress((void**)&s,   g_s);
    cudaGetSymbolAddress((void**)&a3,  g_a3);

    cudaFuncSetAttribute(gemm_mma, cudaFuncAttributeMaxDynamicSharedMemorySize, GEMM_SMEM);

    const int B = BB, S = SS, D = DD;
    const long long MS = (long long)B * S;   // 8192

    // launches 0-3: operand conversion
    conv_split2<<<(int)(MS * D / 256), 256>>>(x, x3, D);
    {
        dim3 tg(D / 32, D / 32, 1);
        transposeY2<<<tg, 256>>>(Wq, wqt, D, D, 0, 0);
        transposeY2<<<tg, 256>>>(Wk, wkt, D, D, 0, 0);
        transposeY2<<<tg, 256>>>(Wv, wvt, D, D, 0, 0);
    }

    // launch 4: fused QKV projections (1536 tiles)
    gemm_mma<<<1536, 128, GEMM_SMEM>>>(1, x3, wqt, wkt, wvt, q3, k3, vf);

    // launch 5 (ncu-captured): scores = Q K^T, triangular tile list
    gemm_mma<<<136 * B, 128, GEMM_SMEM>>>(2, q3, k3, nullptr, nullptr,
                                          s, nullptr, nullptr);

    // launch 6: transpose-split v (depends only on QKV)
    {
        dim3 tg(D / 32, S / 32, B);
        transposeY2<<<tg, 256>>>(vf, vt3, S, D,
                                 (long long)S * D, (long long)D * 2 * S);
    }

    // launch 7: softmax -> split bf16 attn
    softmax2<<<B * S, 256>>>(s, a3, S, 0.03125f);

    // launch 8: out = attn @ V (K-clamped, longest tiles first)
    gemm_mma<<<16 * 8 * B, 128, GEMM_SMEM>>>(3, a3, vt3, nullptr, nullptr,
                                             out, nullptr, nullptr);
}